// round 16
// baseline (speedup 1.0000x reference)
#include <cuda_runtime.h>
#include <cuda_bf16.h>
#include <stdint.h>
#include <math.h>

// Problem constants
#define T 2048
#define B 16
#define D 1024
#define H 512
#define G4 2048          // 4*H gate width
#define NBLK 64          // blocks per direction in recurrent kernel
#define MROWS (T * B)    // 32768 GEMM rows

// ======================= helpers =======================
__device__ __forceinline__ uint32_t smem_to_u32(const void* p) {
    uint32_t a;
    asm("{ .reg .u64 t; cvta.to.shared.u64 t, %1; cvt.u32.u64 %0, t; }" : "=r"(a) : "l"(p));
    return a;
}
__device__ __forceinline__ void ldmat_x4(uint32_t* r, uint32_t addr) {
    asm volatile("ldmatrix.sync.aligned.m8n8.x4.shared.b16 {%0,%1,%2,%3}, [%4];"
                 : "=r"(r[0]), "=r"(r[1]), "=r"(r[2]), "=r"(r[3]) : "r"(addr));
}
__device__ __forceinline__ void ldmat_x2(uint32_t* r, uint32_t addr) {
    asm volatile("ldmatrix.sync.aligned.m8n8.x2.shared.b16 {%0,%1}, [%2];"
                 : "=r"(r[0]), "=r"(r[1]) : "r"(addr));
}
__device__ __forceinline__ void mma16816(float* d, const uint32_t* a, const uint32_t* b) {
    asm volatile(
        "mma.sync.aligned.m16n8k16.row.col.f32.bf16.bf16.f32 "
        "{%0,%1,%2,%3}, {%4,%5,%6,%7}, {%8,%9}, {%0,%1,%2,%3};"
        : "+f"(d[0]), "+f"(d[1]), "+f"(d[2]), "+f"(d[3])
        : "r"(a[0]), "r"(a[1]), "r"(a[2]), "r"(a[3]), "r"(b[0]), "r"(b[1]));
}
__device__ __forceinline__ void cp_async16(uint32_t dst, const void* src) {
    asm volatile("cp.async.cg.shared.global [%0], [%1], 16;" :: "r"(dst), "l"(src));
}
#define CP_COMMIT() asm volatile("cp.async.commit_group;" ::: "memory")
#define CP_WAIT1()  asm volatile("cp.async.wait_group 1;" ::: "memory")

// f32x2 packed math (recurrent kernel)
__device__ __forceinline__ unsigned long long pack2(float lo, float hi) {
    unsigned long long r;
    asm("mov.b64 %0, {%1, %2};" : "=l"(r) : "r"(__float_as_uint(lo)), "r"(__float_as_uint(hi)));
    return r;
}
__device__ __forceinline__ float2 unpack2(unsigned long long v) {
    unsigned int lo, hi;
    asm("mov.b64 {%0, %1}, %2;" : "=r"(lo), "=r"(hi) : "l"(v));
    return make_float2(__uint_as_float(lo), __uint_as_float(hi));
}
__device__ __forceinline__ void ffma2(unsigned long long& d, unsigned long long a,
                                      unsigned long long b) {
    asm("fma.rn.f32x2 %0, %1, %2, %0;" : "+l"(d) : "l"(a), "l"(b));
}

// ======================= scratch globals =======================
__device__ __nv_bfloat16 g_Ahi[MROWS * D];
__device__ __nv_bfloat16 g_Alo[MROWS * D];
__device__ __nv_bfloat16 g_Whi0[G4 * D];
__device__ __nv_bfloat16 g_Wlo0[G4 * D];
__device__ __nv_bfloat16 g_Whi1[G4 * D];
__device__ __nv_bfloat16 g_Wlo1[G4 * D];
__device__ float g_Xg0[MROWS * G4];
__device__ float g_Xg1[MROWS * G4];
__device__ float g_H0f[MROWS * H];
__device__ float g_H0b[MROWS * H];
__device__ float g_H1f[MROWS * H];
__device__ float g_H1b[MROWS * H];
// step flags: [layer*2+dir][block][pad 32 words = 128B line each]
__device__ unsigned int g_flag[4 * NBLK * 32];

// ======================= small kernels =======================
__global__ void bar_reset() {
    g_flag[threadIdx.x * 32] = 0u;     // 256 threads = 4*64 flags
}

__global__ void embed_split(const int* __restrict__ ids, const float* __restrict__ E,
                            __nv_bfloat16* __restrict__ Ahi, __nv_bfloat16* __restrict__ Alo) {
    int row = blockIdx.x;
    int t = row >> 4, b = row & 15;
    int tok = ids[b * T + t];
    const float4* src = (const float4*)(E + (size_t)tok * D);
    float4 v = src[threadIdx.x];
    size_t o = (size_t)row * D + threadIdx.x * 4;
    float f[4] = {v.x, v.y, v.z, v.w};
    __nv_bfloat16 hi[4], lo[4];
    #pragma unroll
    for (int i = 0; i < 4; i++) {
        hi[i] = __float2bfloat16_rn(f[i]);
        lo[i] = __float2bfloat16_rn(f[i] - __bfloat162float(hi[i]));
    }
    *(__nv_bfloat162*)(Ahi + o)     = __halves2bfloat162(hi[0], hi[1]);
    *(__nv_bfloat162*)(Ahi + o + 2) = __halves2bfloat162(hi[2], hi[3]);
    *(__nv_bfloat162*)(Alo + o)     = __halves2bfloat162(lo[0], lo[1]);
    *(__nv_bfloat162*)(Alo + o + 2) = __halves2bfloat162(lo[2], lo[3]);
}

__global__ void fsplit(const float* __restrict__ in, __nv_bfloat16* __restrict__ hi,
                       __nv_bfloat16* __restrict__ lo) {
    size_t i = ((size_t)blockIdx.x * 256 + threadIdx.x) * 4;
    float4 v = *(const float4*)(in + i);
    float f[4] = {v.x, v.y, v.z, v.w};
    __nv_bfloat16 h[4], l[4];
    #pragma unroll
    for (int k = 0; k < 4; k++) {
        h[k] = __float2bfloat16_rn(f[k]);
        l[k] = __float2bfloat16_rn(f[k] - __bfloat162float(h[k]));
    }
    *(__nv_bfloat162*)(hi + i)     = __halves2bfloat162(h[0], h[1]);
    *(__nv_bfloat162*)(hi + i + 2) = __halves2bfloat162(h[2], h[3]);
    *(__nv_bfloat162*)(lo + i)     = __halves2bfloat162(l[0], l[1]);
    *(__nv_bfloat162*)(lo + i + 2) = __halves2bfloat162(l[2], l[3]);
}

__global__ void wsplit(const float* __restrict__ W, __nv_bfloat16* __restrict__ Whi,
                       __nv_bfloat16* __restrict__ Wlo, int K) {
    __shared__ float tile[32][33];
    int k0 = blockIdx.x * 32, n0 = blockIdx.y * 32;
    int tx = threadIdx.x, ty = threadIdx.y;
    #pragma unroll
    for (int j = 0; j < 4; j++)
        tile[ty + j * 8][tx] = W[(size_t)(k0 + ty + j * 8) * G4 + n0 + tx];
    __syncthreads();
    #pragma unroll
    for (int j = 0; j < 4; j++) {
        float v = tile[tx][ty + j * 8];
        __nv_bfloat16 hv = __float2bfloat16_rn(v);
        __nv_bfloat16 lv = __float2bfloat16_rn(v - __bfloat162float(hv));
        size_t o = (size_t)(n0 + ty + j * 8) * K + k0 + tx;
        Whi[o] = hv;
        Wlo[o] = lv;
    }
}

// ======================= mma.sync split-bf16 GEMM (cp.async double-buffered) ==========
#define ASTRIDE 40
#define OFF_AH 0
#define OFF_AL (128 * ASTRIDE)
#define OFF_BH (256 * ASTRIDE)
#define OFF_BL (256 * ASTRIDE + 64 * ASTRIDE)
#define STAGE_ELTS (256 * ASTRIDE + 128 * ASTRIDE)
#define GEMM_SMEM2 (2 * STAGE_ELTS * 2)

__global__ __launch_bounds__(256) void mma_gemm(
    const __nv_bfloat16* __restrict__ Ahi, const __nv_bfloat16* __restrict__ Alo,
    const __nv_bfloat16* __restrict__ Bhi, const __nv_bfloat16* __restrict__ Blo,
    const float* __restrict__ bias, float* __restrict__ C, int Ka) {
    extern __shared__ __nv_bfloat16 smem2[];
    int tid = threadIdx.x;
    int wid = tid >> 5, lane = tid & 31;
    int wm = wid & 3, wn = wid >> 2;
    int g = lane >> 2, tq = lane & 3;
    int nbase = blockIdx.x * 64;
    int mbase = blockIdx.y * 128;
    uint32_t sbase = smem_to_u32(smem2);

    int a_row0 = tid >> 2, a_ch = (tid & 3) << 3;
    int b_row  = tid >> 2, b_ch = (tid & 3) << 3;

    float acc[2][4][4];
    #pragma unroll
    for (int mt = 0; mt < 2; mt++)
        #pragma unroll
        for (int nt = 0; nt < 4; nt++)
            #pragma unroll
            for (int e = 0; e < 4; e++) acc[mt][nt][e] = 0.0f;

    int a_sub = lane >> 3;
    int a_row_off = (lane & 7) + ((a_sub & 1) << 3);
    int a_k_off = (a_sub >> 1) << 3;
    int b_row_off = lane & 7;
    int b_k_off = ((lane >> 3) & 1) << 3;

    int nkt = Ka >> 5;

    #define LOAD_STAGE(KT, ST) do {                                              \
        int so = (ST) * STAGE_ELTS;                                              \
        int kc = (KT) << 5;                                                      \
        _Pragma("unroll")                                                        \
        for (int j = 0; j < 2; j++) {                                            \
            int row = a_row0 + j * 64;                                           \
            size_t go = (size_t)(mbase + row) * Ka + kc + a_ch;                  \
            uint32_t ds = sbase + (uint32_t)(so + row * ASTRIDE + a_ch) * 2;     \
            cp_async16(ds + OFF_AH * 2, Ahi + go);                               \
            cp_async16(ds + OFF_AL * 2, Alo + go);                               \
        }                                                                        \
        {                                                                        \
            size_t go = (size_t)(nbase + b_row) * Ka + kc + b_ch;                \
            uint32_t ds = sbase + (uint32_t)(so + b_row * ASTRIDE + b_ch) * 2;   \
            cp_async16(ds + OFF_BH * 2, Bhi + go);                               \
            cp_async16(ds + OFF_BL * 2, Blo + go);                               \
        }                                                                        \
        CP_COMMIT();                                                             \
    } while (0)

    LOAD_STAGE(0, 0);
    LOAD_STAGE(1, 1);

    for (int kt = 0; kt < nkt; kt++) {
        CP_WAIT1();
        __syncthreads();
        int st = kt & 1;
        uint32_t uA = sbase + (uint32_t)(st * STAGE_ELTS) * 2;
        uint32_t uB = uA + (uint32_t)OFF_BH * 2;

        #pragma unroll
        for (int kk = 0; kk < 32; kk += 16) {
            uint32_t aH[2][4], aL[2][4], bH[4][2], bL[4][2];
            #pragma unroll
            for (int mt = 0; mt < 2; mt++) {
                uint32_t off = ((wm * 32 + mt * 16 + a_row_off) * ASTRIDE
                                + kk + a_k_off) * 2;
                ldmat_x4(aH[mt], uA + OFF_AH * 2 + off);
                ldmat_x4(aL[mt], uA + OFF_AL * 2 + off);
            }
            #pragma unroll
            for (int nt = 0; nt < 4; nt++) {
                uint32_t off = ((wn * 32 + nt * 8 + b_row_off) * ASTRIDE
                                + kk + b_k_off) * 2;
                ldmat_x2(bH[nt], uB + off);
                ldmat_x2(bL[nt], uB + (OFF_BL - OFF_BH) * 2 + off);
            }
            #pragma unroll
            for (int mt = 0; mt < 2; mt++)
                #pragma unroll
                for (int nt = 0; nt < 4; nt++) {
                    mma16816(acc[mt][nt], aH[mt], bH[nt]);
                    mma16816(acc[mt][nt], aH[mt], bL[nt]);
                    mma16816(acc[mt][nt], aL[mt], bH[nt]);
                }
        }
        __syncthreads();
        if (kt + 2 < nkt) LOAD_STAGE(kt + 2, st);
    }

    #pragma unroll
    for (int mt = 0; mt < 2; mt++) {
        int r0 = mbase + wm * 32 + mt * 16 + g;
        #pragma unroll
        for (int nt = 0; nt < 4; nt++) {
            int col = nbase + wn * 32 + nt * 8 + tq * 2;
            float2 bv = *(const float2*)(bias + col);
            float2 v0 = make_float2(acc[mt][nt][0] + bv.x, acc[mt][nt][1] + bv.y);
            float2 v1 = make_float2(acc[mt][nt][2] + bv.x, acc[mt][nt][3] + bv.y);
            *(float2*)(C + (size_t)r0 * G4 + col) = v0;
            *(float2*)(C + (size_t)(r0 + 8) * G4 + col) = v1;
        }
    }
    #undef LOAD_STAGE
}

// ======================= persistent recurrent kernel =======================
// Step sync: per-block release flags (128B-padded) + 64 acquire pollers.
// No same-address atomics -> no L2 atomic serialization.
#define REC_SMEM_FLOATS (16 * 512 + 512 * 17 + 16 * 33)
__global__ __launch_bounds__(256, 1) void lstm_rec(
    const float* __restrict__ WhF, const float* __restrict__ WhB,
    const float* __restrict__ XgF, const float* __restrict__ XgB,
    float* __restrict__ HF, float* __restrict__ HB, int layer) {
    extern __shared__ float sm[];
    float* sH = sm;
    float* sR = sH + 16 * 512;
    float* sG = sR + 512 * 17;

    int dir = blockIdx.x / NBLK;
    int blk = blockIdx.x - dir * NBLK;
    const float* Wh = dir ? WhB : WhF;
    const float* Xg = dir ? XgB : XgF;
    float* Hout = dir ? HB : HF;
    unsigned int* flags = g_flag + (layer * 2 + dir) * NBLK * 32;
    int jbase = blk * 8;
    int tid = threadIdx.x;

    int cp  = tid & 15;
    int ksl = tid >> 4;
    int c0 = 2 * cp, c1 = c0 + 1;
    int gc0 = (c0 >> 3) * H + (c0 & 7) + jbase;
    int gc1 = (c1 >> 3) * H + (c1 & 7) + jbase;

    unsigned long long w0[16], w1[16];
    #pragma unroll
    for (int k2 = 0; k2 < 16; k2++) {
        int k = ksl * 32 + 2 * k2;
        w0[k2] = pack2(Wh[(size_t)k * G4 + gc0], Wh[(size_t)(k + 1) * G4 + gc0]);
        w1[k2] = pack2(Wh[(size_t)k * G4 + gc1], Wh[(size_t)(k + 1) * G4 + gc1]);
    }

    int b_e  = tid & 15;
    int jl_e = (tid >> 4) & 7;
    float cst = 0.0f;

    for (int s = 0; s < T; s++) {
        int t = dir ? (T - 1 - s) : s;

        if (s == 0) {
            for (int i = tid; i < (16 * 512) / 4; i += 256)
                *(float4*)&sH[i * 4] = make_float4(0.f, 0.f, 0.f, 0.f);
        } else {
            int tp = dir ? (t + 1) : (t - 1);
            const float* hp = Hout + (size_t)tp * (B * H);
            for (int i = tid; i < (B * H) / 4; i += 256) {
                float4 v = __ldcg((const float4*)(hp + i * 4));
                *(float4*)&sH[i * 4] = v;
            }
        }

        float x0 = 0.f, x1 = 0.f, x2 = 0.f, x3 = 0.f;
        if (tid < 128) {
            const float* xp = Xg + (size_t)t * (B * G4) + b_e * G4 + jbase + jl_e;
            x0 = xp[0];
            x1 = xp[H];
            x2 = xp[2 * H];
            x3 = xp[3 * H];
        }
        __syncthreads();

        #pragma unroll 4
        for (int b = 0; b < 16; b++) {
            const unsigned long long* hp =
                (const unsigned long long*)(sH + b * 512 + ksl * 32);
            unsigned long long a0 = 0ull, a1 = 0ull;
            #pragma unroll
            for (int k2 = 0; k2 < 16; k2++) {
                unsigned long long h2 = hp[k2];
                ffma2(a0, h2, w0[k2]);
                ffma2(a1, h2, w1[k2]);
            }
            float2 f0 = unpack2(a0);
            float2 f1 = unpack2(a1);
            sR[(b * 32 + c0) * 17 + ksl] = f0.x + f0.y;
            sR[(b * 32 + c1) * 17 + ksl] = f1.x + f1.y;
        }
        __syncthreads();

        #pragma unroll
        for (int rep = 0; rep < 2; rep++) {
            int o = tid + rep * 256;
            float ssum = 0.f;
            #pragma unroll
            for (int j = 0; j < 16; j++) ssum += sR[o * 17 + j];
            sG[(o >> 5) * 33 + (o & 31)] = ssum;
        }
        __syncthreads();

        if (tid < 128) {
            float gi = sG[b_e * 33 + jl_e] + x0;
            float gg = sG[b_e * 33 + 8 + jl_e] + x1;
            float gf = sG[b_e * 33 + 16 + jl_e] + x2 + 1.0f;
            float go = sG[b_e * 33 + 24 + jl_e] + x3;
            float iv = 1.0f / (1.0f + expf(-gi));
            float gv = tanhf(gg);
            float fv = 1.0f / (1.0f + expf(-gf));
            float ov = 1.0f / (1.0f + expf(-go));
            cst = fv * cst + iv * gv;
            float hv = ov * tanhf(cst);
            __stcg(Hout + (size_t)t * (B * H) + b_e * H + jbase + jl_e, hv);
        }

        __syncthreads();                 // all h stores issued (program order)
        if (s + 1 < T) {
            unsigned int tgt = (unsigned int)(s + 1);
            if (tid == 0) {
                __threadfence();         // publish this block's h stores (CG grid-sync pattern)
                asm volatile("st.release.gpu.global.u32 [%0], %1;"
                             :: "l"(flags + blk * 32), "r"(tgt) : "memory");
            }
            if (tid < NBLK) {
                unsigned int v;
                do {
                    asm volatile("ld.acquire.gpu.global.u32 %0, [%1];"
                                 : "=r"(v) : "l"(flags + tid * 32) : "memory");
                } while (v < tgt);
            }
            __syncthreads();
        }
    }
}

// ======================= output assembly =======================
__global__ void assemble(const float* __restrict__ H1f, const float* __restrict__ H1b,
                         float* __restrict__ out) {
    int b = blockIdx.x >> 11;
    int t = blockIdx.x & 2047;
    float4* dst = (float4*)(out + (size_t)blockIdx.x * 1024);
    const float4* f = (const float4*)(H1f + ((size_t)t * B + b) * H);
    const float4* bk = (const float4*)(H1b + ((size_t)t * B + b) * H);
    int i = threadIdx.x;
    dst[i] = (i < 128) ? f[i] : bk[i - 128];
}

// ======================= launch =======================
extern "C" void kernel_launch(void* const* d_in, const int* in_sizes, int n_in,
                              void* d_out, int out_size) {
    const int*   ids = (const int*)d_in[0];
    const float* E   = (const float*)d_in[1];
    const float* fW0 = (const float*)d_in[2];
    const float* fb0 = (const float*)d_in[3];
    const float* fW1 = (const float*)d_in[4];
    const float* fb1 = (const float*)d_in[5];
    const float* bW0 = (const float*)d_in[6];
    const float* bb0 = (const float*)d_in[7];
    const float* bW1 = (const float*)d_in[8];
    const float* bb1 = (const float*)d_in[9];
    float* out = (float*)d_out;

    __nv_bfloat16 *Ahi, *Alo, *Whi0, *Wlo0, *Whi1, *Wlo1;
    float *Xg0, *Xg1, *H0f, *H0b, *H1f, *H1b;
    cudaGetSymbolAddress((void**)&Ahi,  g_Ahi);
    cudaGetSymbolAddress((void**)&Alo,  g_Alo);
    cudaGetSymbolAddress((void**)&Whi0, g_Whi0);
    cudaGetSymbolAddress((void**)&Wlo0, g_Wlo0);
    cudaGetSymbolAddress((void**)&Whi1, g_Whi1);
    cudaGetSymbolAddress((void**)&Wlo1, g_Wlo1);
    cudaGetSymbolAddress((void**)&Xg0,  g_Xg0);
    cudaGetSymbolAddress((void**)&Xg1,  g_Xg1);
    cudaGetSymbolAddress((void**)&H0f,  g_H0f);
    cudaGetSymbolAddress((void**)&H0b,  g_H0b);
    cudaGetSymbolAddress((void**)&H1f,  g_H1f);
    cudaGetSymbolAddress((void**)&H1b,  g_H1b);

    const int REC_SMEM = REC_SMEM_FLOATS * 4;
    cudaFuncSetAttribute(lstm_rec, cudaFuncAttributeMaxDynamicSharedMemorySize, REC_SMEM);
    cudaFuncSetAttribute(mma_gemm, cudaFuncAttributeMaxDynamicSharedMemorySize, GEMM_SMEM2);

    dim3 gt0(D / 32, G4 / 32), gt1(H / 32, G4 / 32), bt(32, 8);
    dim3 gg(G4 / 64, MROWS / 128);

    bar_reset<<<1, 256>>>();
    embed_split<<<MROWS, 256>>>(ids, E, Ahi, Alo);
    wsplit<<<gt0, bt>>>(fW0, Whi0, Wlo0, D);
    wsplit<<<gt0, bt>>>(bW0, Whi1, Wlo1, D);
    mma_gemm<<<gg, 256, GEMM_SMEM2>>>(Ahi, Alo, Whi0, Wlo0, fb0, Xg0, D);
    mma_gemm<<<gg, 256, GEMM_SMEM2>>>(Ahi, Alo, Whi1, Wlo1, bb0, Xg1, D);
    lstm_rec<<<2 * NBLK, 256, REC_SMEM>>>(fW0 + (size_t)D * G4, bW0 + (size_t)D * G4,
                                          Xg0, Xg1, H0f, H0b, 0);
    fsplit<<<MROWS * H / 1024, 256>>>(H0f, Ahi, Alo);
    wsplit<<<gt1, bt>>>(fW1, Whi0, Wlo0, H);
    mma_gemm<<<gg, 256, GEMM_SMEM2>>>(Ahi, Alo, Whi0, Wlo0, fb1, Xg0, H);
    fsplit<<<MROWS * H / 1024, 256>>>(H0b, Ahi, Alo);
    wsplit<<<gt1, bt>>>(bW1, Whi1, Wlo1, H);
    mma_gemm<<<gg, 256, GEMM_SMEM2>>>(Ahi, Alo, Whi1, Wlo1, bb1, Xg1, H);
    lstm_rec<<<2 * NBLK, 256, REC_SMEM>>>(fW1 + (size_t)H * G4, bW1 + (size_t)H * G4,
                                          Xg0, Xg1, H1f, H1b, 1);
    assemble<<<B * T, 256>>>(H1f, H1b, out);
}

// round 17
// speedup vs baseline: 1.0400x; 1.0400x over previous
#include <cuda_runtime.h>
#include <cuda_bf16.h>
#include <stdint.h>
#include <math.h>

// Problem constants
#define T 2048
#define B 16
#define D 1024
#define H 512
#define G4 2048          // 4*H gate width
#define NBLK 64          // blocks per direction in recurrent kernel
#define MROWS (T * B)    // 32768 GEMM rows

// ======================= helpers =======================
__device__ __forceinline__ uint32_t smem_to_u32(const void* p) {
    uint32_t a;
    asm("{ .reg .u64 t; cvta.to.shared.u64 t, %1; cvt.u32.u64 %0, t; }" : "=r"(a) : "l"(p));
    return a;
}
__device__ __forceinline__ void ldmat_x4(uint32_t* r, uint32_t addr) {
    asm volatile("ldmatrix.sync.aligned.m8n8.x4.shared.b16 {%0,%1,%2,%3}, [%4];"
                 : "=r"(r[0]), "=r"(r[1]), "=r"(r[2]), "=r"(r[3]) : "r"(addr));
}
__device__ __forceinline__ void ldmat_x2(uint32_t* r, uint32_t addr) {
    asm volatile("ldmatrix.sync.aligned.m8n8.x2.shared.b16 {%0,%1}, [%2];"
                 : "=r"(r[0]), "=r"(r[1]) : "r"(addr));
}
__device__ __forceinline__ void mma16816(float* d, const uint32_t* a, const uint32_t* b) {
    asm volatile(
        "mma.sync.aligned.m16n8k16.row.col.f32.bf16.bf16.f32 "
        "{%0,%1,%2,%3}, {%4,%5,%6,%7}, {%8,%9}, {%0,%1,%2,%3};"
        : "+f"(d[0]), "+f"(d[1]), "+f"(d[2]), "+f"(d[3])
        : "r"(a[0]), "r"(a[1]), "r"(a[2]), "r"(a[3]), "r"(b[0]), "r"(b[1]));
}
__device__ __forceinline__ void cp_async16(uint32_t dst, const void* src) {
    asm volatile("cp.async.cg.shared.global [%0], [%1], 16;" :: "r"(dst), "l"(src));
}
#define CP_COMMIT() asm volatile("cp.async.commit_group;" ::: "memory")
#define CP_WAIT1()  asm volatile("cp.async.wait_group 1;" ::: "memory")

// f32x2 packed math (recurrent kernel)
__device__ __forceinline__ unsigned long long pack2(float lo, float hi) {
    unsigned long long r;
    asm("mov.b64 %0, {%1, %2};" : "=l"(r) : "r"(__float_as_uint(lo)), "r"(__float_as_uint(hi)));
    return r;
}
__device__ __forceinline__ float2 unpack2(unsigned long long v) {
    unsigned int lo, hi;
    asm("mov.b64 {%0, %1}, %2;" : "=r"(lo), "=r"(hi) : "l"(v));
    return make_float2(__uint_as_float(lo), __uint_as_float(hi));
}
__device__ __forceinline__ void ffma2(unsigned long long& d, unsigned long long a,
                                      unsigned long long b) {
    asm("fma.rn.f32x2 %0, %1, %2, %0;" : "+l"(d) : "l"(a), "l"(b));
}

// ======================= scratch globals =======================
__device__ __nv_bfloat16 g_Ahi[MROWS * D];
__device__ __nv_bfloat16 g_Alo[MROWS * D];
__device__ __nv_bfloat16 g_Whi0[G4 * D];
__device__ __nv_bfloat16 g_Wlo0[G4 * D];
__device__ __nv_bfloat16 g_Whi1[G4 * D];
__device__ __nv_bfloat16 g_Wlo1[G4 * D];
__device__ float g_Xg0[MROWS * G4];
__device__ float g_Xg1[MROWS * G4];
__device__ float g_H0f[MROWS * H];
__device__ float g_H0b[MROWS * H];
__device__ float g_H1f[MROWS * H];
__device__ float g_H1b[MROWS * H];
__device__ unsigned int g_bar[4];                 // {L0F, L0B, L1F, L1B}

// ======================= small kernels =======================
__global__ void bar_reset() {
    if (threadIdx.x < 4) g_bar[threadIdx.x] = 0u;
}

__global__ void embed_split(const int* __restrict__ ids, const float* __restrict__ E,
                            __nv_bfloat16* __restrict__ Ahi, __nv_bfloat16* __restrict__ Alo) {
    int row = blockIdx.x;
    int t = row >> 4, b = row & 15;
    int tok = ids[b * T + t];
    const float4* src = (const float4*)(E + (size_t)tok * D);
    float4 v = src[threadIdx.x];
    size_t o = (size_t)row * D + threadIdx.x * 4;
    float f[4] = {v.x, v.y, v.z, v.w};
    __nv_bfloat16 hi[4], lo[4];
    #pragma unroll
    for (int i = 0; i < 4; i++) {
        hi[i] = __float2bfloat16_rn(f[i]);
        lo[i] = __float2bfloat16_rn(f[i] - __bfloat162float(hi[i]));
    }
    *(__nv_bfloat162*)(Ahi + o)     = __halves2bfloat162(hi[0], hi[1]);
    *(__nv_bfloat162*)(Ahi + o + 2) = __halves2bfloat162(hi[2], hi[3]);
    *(__nv_bfloat162*)(Alo + o)     = __halves2bfloat162(lo[0], lo[1]);
    *(__nv_bfloat162*)(Alo + o + 2) = __halves2bfloat162(lo[2], lo[3]);
}

__global__ void fsplit(const float* __restrict__ in, __nv_bfloat16* __restrict__ hi,
                       __nv_bfloat16* __restrict__ lo) {
    size_t i = ((size_t)blockIdx.x * 256 + threadIdx.x) * 4;
    float4 v = *(const float4*)(in + i);
    float f[4] = {v.x, v.y, v.z, v.w};
    __nv_bfloat16 h[4], l[4];
    #pragma unroll
    for (int k = 0; k < 4; k++) {
        h[k] = __float2bfloat16_rn(f[k]);
        l[k] = __float2bfloat16_rn(f[k] - __bfloat162float(h[k]));
    }
    *(__nv_bfloat162*)(hi + i)     = __halves2bfloat162(h[0], h[1]);
    *(__nv_bfloat162*)(hi + i + 2) = __halves2bfloat162(h[2], h[3]);
    *(__nv_bfloat162*)(lo + i)     = __halves2bfloat162(l[0], l[1]);
    *(__nv_bfloat162*)(lo + i + 2) = __halves2bfloat162(l[2], l[3]);
}

__global__ void wsplit(const float* __restrict__ W, __nv_bfloat16* __restrict__ Whi,
                       __nv_bfloat16* __restrict__ Wlo, int K) {
    __shared__ float tile[32][33];
    int k0 = blockIdx.x * 32, n0 = blockIdx.y * 32;
    int tx = threadIdx.x, ty = threadIdx.y;
    #pragma unroll
    for (int j = 0; j < 4; j++)
        tile[ty + j * 8][tx] = W[(size_t)(k0 + ty + j * 8) * G4 + n0 + tx];
    __syncthreads();
    #pragma unroll
    for (int j = 0; j < 4; j++) {
        float v = tile[tx][ty + j * 8];
        __nv_bfloat16 hv = __float2bfloat16_rn(v);
        __nv_bfloat16 lv = __float2bfloat16_rn(v - __bfloat162float(hv));
        size_t o = (size_t)(n0 + ty + j * 8) * K + k0 + tx;
        Whi[o] = hv;
        Wlo[o] = lv;
    }
}

// ======================= mma.sync split-bf16 GEMM (3-stage cp.async pipeline) ==========
// Block: 128(M) x 64(N), 256 threads = 8 warps (4M x 2N), warp tile 32x32, BK=32.
// One __syncthreads per k-iter; loads for kt+2 issued BEFORE compute of kt.
#define ASTRIDE 40
#define OFF_AH 0
#define OFF_AL (128 * ASTRIDE)
#define OFF_BH (256 * ASTRIDE)
#define OFF_BL (256 * ASTRIDE + 64 * ASTRIDE)
#define STAGE_ELTS (256 * ASTRIDE + 128 * ASTRIDE)   // 15360 bf16
#define GEMM_SMEM3 (3 * STAGE_ELTS * 2)              // 92160 bytes

__global__ __launch_bounds__(256) void mma_gemm(
    const __nv_bfloat16* __restrict__ Ahi, const __nv_bfloat16* __restrict__ Alo,
    const __nv_bfloat16* __restrict__ Bhi, const __nv_bfloat16* __restrict__ Blo,
    const float* __restrict__ bias, float* __restrict__ C, int Ka) {
    extern __shared__ __nv_bfloat16 smem2[];
    int tid = threadIdx.x;
    int wid = tid >> 5, lane = tid & 31;
    int wm = wid & 3, wn = wid >> 2;
    int g = lane >> 2, tq = lane & 3;
    int nbase = blockIdx.x * 64;
    int mbase = blockIdx.y * 128;
    uint32_t sbase = smem_to_u32(smem2);

    int a_row0 = tid >> 2, a_ch = (tid & 3) << 3;
    int b_row  = tid >> 2, b_ch = (tid & 3) << 3;

    float acc[2][4][4];
    #pragma unroll
    for (int mt = 0; mt < 2; mt++)
        #pragma unroll
        for (int nt = 0; nt < 4; nt++)
            #pragma unroll
            for (int e = 0; e < 4; e++) acc[mt][nt][e] = 0.0f;

    int a_sub = lane >> 3;
    int a_row_off = (lane & 7) + ((a_sub & 1) << 3);
    int a_k_off = (a_sub >> 1) << 3;
    int b_row_off = lane & 7;
    int b_k_off = ((lane >> 3) & 1) << 3;

    int nkt = Ka >> 5;

    #define LOAD_STAGE(KT, ST) do {                                              \
        int so = (ST) * STAGE_ELTS;                                              \
        int kc = (KT) << 5;                                                      \
        _Pragma("unroll")                                                        \
        for (int j = 0; j < 2; j++) {                                            \
            int row = a_row0 + j * 64;                                           \
            size_t go = (size_t)(mbase + row) * Ka + kc + a_ch;                  \
            uint32_t ds = sbase + (uint32_t)(so + row * ASTRIDE + a_ch) * 2;     \
            cp_async16(ds + OFF_AH * 2, Ahi + go);                               \
            cp_async16(ds + OFF_AL * 2, Alo + go);                               \
        }                                                                        \
        {                                                                        \
            size_t go = (size_t)(nbase + b_row) * Ka + kc + b_ch;                \
            uint32_t ds = sbase + (uint32_t)(so + b_row * ASTRIDE + b_ch) * 2;   \
            cp_async16(ds + OFF_BH * 2, Bhi + go);                               \
            cp_async16(ds + OFF_BL * 2, Blo + go);                               \
        }                                                                        \
        CP_COMMIT();                                                             \
    } while (0)

    LOAD_STAGE(0, 0);
    LOAD_STAGE(1, 1);

    for (int kt = 0; kt < nkt; kt++) {
        CP_WAIT1();                      // tile kt's group complete
        __syncthreads();                 // cp.async smem visible; stage (kt-1)%3 free
        // prefetch tile kt+2 into stage (kt+2)%3 == (kt-1)%3 (just freed)
        if (kt + 2 < nkt) LOAD_STAGE(kt + 2, (kt + 2) % 3);

        int st = kt % 3;
        uint32_t uA = sbase + (uint32_t)(st * STAGE_ELTS) * 2;
        uint32_t uB = uA + (uint32_t)OFF_BH * 2;

        #pragma unroll
        for (int kk = 0; kk < 32; kk += 16) {
            uint32_t aH[2][4], aL[2][4], bH[4][2], bL[4][2];
            #pragma unroll
            for (int mt = 0; mt < 2; mt++) {
                uint32_t off = ((wm * 32 + mt * 16 + a_row_off) * ASTRIDE
                                + kk + a_k_off) * 2;
                ldmat_x4(aH[mt], uA + OFF_AH * 2 + off);
                ldmat_x4(aL[mt], uA + OFF_AL * 2 + off);
            }
            #pragma unroll
            for (int nt = 0; nt < 4; nt++) {
                uint32_t off = ((wn * 32 + nt * 8 + b_row_off) * ASTRIDE
                                + kk + b_k_off) * 2;
                ldmat_x2(bH[nt], uB + off);
                ldmat_x2(bL[nt], uB + (OFF_BL - OFF_BH) * 2 + off);
            }
            #pragma unroll
            for (int mt = 0; mt < 2; mt++)
                #pragma unroll
                for (int nt = 0; nt < 4; nt++) {
                    mma16816(acc[mt][nt], aH[mt], bH[nt]);
                    mma16816(acc[mt][nt], aH[mt], bL[nt]);
                    mma16816(acc[mt][nt], aL[mt], bH[nt]);
                }
        }
    }

    #pragma unroll
    for (int mt = 0; mt < 2; mt++) {
        int r0 = mbase + wm * 32 + mt * 16 + g;
        #pragma unroll
        for (int nt = 0; nt < 4; nt++) {
            int col = nbase + wn * 32 + nt * 8 + tq * 2;
            float2 bv = *(const float2*)(bias + col);
            float2 v0 = make_float2(acc[mt][nt][0] + bv.x, acc[mt][nt][1] + bv.y);
            float2 v1 = make_float2(acc[mt][nt][2] + bv.x, acc[mt][nt][3] + bv.y);
            *(float2*)(C + (size_t)r0 * G4 + col) = v0;
            *(float2*)(C + (size_t)(r0 + 8) * G4 + col) = v1;
        }
    }
    #undef LOAD_STAGE
}

// ======================= persistent recurrent kernel =======================
// Step sync: R13-proven atomic counter barrier, with leader-only fences (CG pattern).
#define REC_SMEM_FLOATS (16 * 512 + 512 * 17 + 16 * 33)
__global__ __launch_bounds__(256, 1) void lstm_rec(
    const float* __restrict__ WhF, const float* __restrict__ WhB,
    const float* __restrict__ XgF, const float* __restrict__ XgB,
    float* __restrict__ HF, float* __restrict__ HB, int layer) {
    extern __shared__ float sm[];
    float* sH = sm;
    float* sR = sH + 16 * 512;
    float* sG = sR + 512 * 17;

    int dir = blockIdx.x / NBLK;
    int blk = blockIdx.x - dir * NBLK;
    const float* Wh = dir ? WhB : WhF;
    const float* Xg = dir ? XgB : XgF;
    float* Hout = dir ? HB : HF;
    unsigned int* bar = &g_bar[layer * 2 + dir];
    int jbase = blk * 8;
    int tid = threadIdx.x;

    int cp  = tid & 15;
    int ksl = tid >> 4;
    int c0 = 2 * cp, c1 = c0 + 1;
    int gc0 = (c0 >> 3) * H + (c0 & 7) + jbase;
    int gc1 = (c1 >> 3) * H + (c1 & 7) + jbase;

    unsigned long long w0[16], w1[16];
    #pragma unroll
    for (int k2 = 0; k2 < 16; k2++) {
        int k = ksl * 32 + 2 * k2;
        w0[k2] = pack2(Wh[(size_t)k * G4 + gc0], Wh[(size_t)(k + 1) * G4 + gc0]);
        w1[k2] = pack2(Wh[(size_t)k * G4 + gc1], Wh[(size_t)(k + 1) * G4 + gc1]);
    }

    int b_e  = tid & 15;
    int jl_e = (tid >> 4) & 7;
    float cst = 0.0f;

    for (int s = 0; s < T; s++) {
        int t = dir ? (T - 1 - s) : s;

        if (s == 0) {
            for (int i = tid; i < (16 * 512) / 4; i += 256)
                *(float4*)&sH[i * 4] = make_float4(0.f, 0.f, 0.f, 0.f);
        } else {
            int tp = dir ? (t + 1) : (t - 1);
            const float* hp = Hout + (size_t)tp * (B * H);
            for (int i = tid; i < (B * H) / 4; i += 256) {
                float4 v = __ldcg((const float4*)(hp + i * 4));
                *(float4*)&sH[i * 4] = v;
            }
        }

        float x0 = 0.f, x1 = 0.f, x2 = 0.f, x3 = 0.f;
        if (tid < 128) {
            const float* xp = Xg + (size_t)t * (B * G4) + b_e * G4 + jbase + jl_e;
            x0 = xp[0];
            x1 = xp[H];
            x2 = xp[2 * H];
            x3 = xp[3 * H];
        }
        __syncthreads();

        #pragma unroll 4
        for (int b = 0; b < 16; b++) {
            const unsigned long long* hp =
                (const unsigned long long*)(sH + b * 512 + ksl * 32);
            unsigned long long a0 = 0ull, a1 = 0ull;
            #pragma unroll
            for (int k2 = 0; k2 < 16; k2++) {
                unsigned long long h2 = hp[k2];
                ffma2(a0, h2, w0[k2]);
                ffma2(a1, h2, w1[k2]);
            }
            float2 f0 = unpack2(a0);
            float2 f1 = unpack2(a1);
            sR[(b * 32 + c0) * 17 + ksl] = f0.x + f0.y;
            sR[(b * 32 + c1) * 17 + ksl] = f1.x + f1.y;
        }
        __syncthreads();

        #pragma unroll
        for (int rep = 0; rep < 2; rep++) {
            int o = tid + rep * 256;
            float ssum = 0.f;
            #pragma unroll
            for (int j = 0; j < 16; j++) ssum += sR[o * 17 + j];
            sG[(o >> 5) * 33 + (o & 31)] = ssum;
        }
        __syncthreads();

        if (tid < 128) {
            float gi = sG[b_e * 33 + jl_e] + x0;
            float gg = sG[b_e * 33 + 8 + jl_e] + x1;
            float gf = sG[b_e * 33 + 16 + jl_e] + x2 + 1.0f;
            float go = sG[b_e * 33 + 24 + jl_e] + x3;
            float iv = 1.0f / (1.0f + expf(-gi));
            float gv = tanhf(gg);
            float fv = 1.0f / (1.0f + expf(-gf));
            float ov = 1.0f / (1.0f + expf(-go));
            cst = fv * cst + iv * gv;
            float hv = ov * tanhf(cst);
            __stcg(Hout + (size_t)t * (B * H) + b_e * H + jbase + jl_e, hv);
        }

        __syncthreads();                 // all h stores issued
        if (s + 1 < T) {
            if (tid == 0) {
                __threadfence();         // leader-only release (CG grid-sync pattern)
                atomicAdd(bar, 1u);
                unsigned int tgt = (unsigned int)(s + 1) * NBLK;
                while (*((volatile unsigned int*)bar) < tgt) { }
                __threadfence();         // acquire
            }
            __syncthreads();
        }
    }
}

// ======================= output assembly =======================
__global__ void assemble(const float* __restrict__ H1f, const float* __restrict__ H1b,
                         float* __restrict__ out) {
    int b = blockIdx.x >> 11;
    int t = blockIdx.x & 2047;
    float4* dst = (float4*)(out + (size_t)blockIdx.x * 1024);
    const float4* f = (const float4*)(H1f + ((size_t)t * B + b) * H);
    const float4* bk = (const float4*)(H1b + ((size_t)t * B + b) * H);
    int i = threadIdx.x;
    dst[i] = (i < 128) ? f[i] : bk[i - 128];
}

// ======================= launch =======================
extern "C" void kernel_launch(void* const* d_in, const int* in_sizes, int n_in,
                              void* d_out, int out_size) {
    const int*   ids = (const int*)d_in[0];
    const float* E   = (const float*)d_in[1];
    const float* fW0 = (const float*)d_in[2];
    const float* fb0 = (const float*)d_in[3];
    const float* fW1 = (const float*)d_in[4];
    const float* fb1 = (const float*)d_in[5];
    const float* bW0 = (const float*)d_in[6];
    const float* bb0 = (const float*)d_in[7];
    const float* bW1 = (const float*)d_in[8];
    const float* bb1 = (const float*)d_in[9];
    float* out = (float*)d_out;

    __nv_bfloat16 *Ahi, *Alo, *Whi0, *Wlo0, *Whi1, *Wlo1;
    float *Xg0, *Xg1, *H0f, *H0b, *H1f, *H1b;
    cudaGetSymbolAddress((void**)&Ahi,  g_Ahi);
    cudaGetSymbolAddress((void**)&Alo,  g_Alo);
    cudaGetSymbolAddress((void**)&Whi0, g_Whi0);
    cudaGetSymbolAddress((void**)&Wlo0, g_Wlo0);
    cudaGetSymbolAddress((void**)&Whi1, g_Whi1);
    cudaGetSymbolAddress((void**)&Wlo1, g_Wlo1);
    cudaGetSymbolAddress((void**)&Xg0,  g_Xg0);
    cudaGetSymbolAddress((void**)&Xg1,  g_Xg1);
    cudaGetSymbolAddress((void**)&H0f,  g_H0f);
    cudaGetSymbolAddress((void**)&H0b,  g_H0b);
    cudaGetSymbolAddress((void**)&H1f,  g_H1f);
    cudaGetSymbolAddress((void**)&H1b,  g_H1b);

    const int REC_SMEM = REC_SMEM_FLOATS * 4;
    cudaFuncSetAttribute(lstm_rec, cudaFuncAttributeMaxDynamicSharedMemorySize, REC_SMEM);
    cudaFuncSetAttribute(mma_gemm, cudaFuncAttributeMaxDynamicSharedMemorySize, GEMM_SMEM3);

    dim3 gt0(D / 32, G4 / 32), gt1(H / 32, G4 / 32), bt(32, 8);
    dim3 gg(G4 / 64, MROWS / 128);

    bar_reset<<<1, 32>>>();
    embed_split<<<MROWS, 256>>>(ids, E, Ahi, Alo);
    wsplit<<<gt0, bt>>>(fW0, Whi0, Wlo0, D);
    wsplit<<<gt0, bt>>>(bW0, Whi1, Wlo1, D);
    mma_gemm<<<gg, 256, GEMM_SMEM3>>>(Ahi, Alo, Whi0, Wlo0, fb0, Xg0, D);
    mma_gemm<<<gg, 256, GEMM_SMEM3>>>(Ahi, Alo, Whi1, Wlo1, bb0, Xg1, D);
    lstm_rec<<<2 * NBLK, 256, REC_SMEM>>>(fW0 + (size_t)D * G4, bW0 + (size_t)D * G4,
                                          Xg0, Xg1, H0f, H0b, 0);
    fsplit<<<MROWS * H / 1024, 256>>>(H0f, Ahi, Alo);
    wsplit<<<gt1, bt>>>(fW1, Whi0, Wlo0, H);
    mma_gemm<<<gg, 256, GEMM_SMEM3>>>(Ahi, Alo, Whi0, Wlo0, fb1, Xg0, H);
    fsplit<<<MROWS * H / 1024, 256>>>(H0b, Ahi, Alo);
    wsplit<<<gt1, bt>>>(bW1, Whi1, Wlo1, H);
    mma_gemm<<<gg, 256, GEMM_SMEM3>>>(Ahi, Alo, Whi1, Wlo1, bb1, Xg1, H);
    lstm_rec<<<2 * NBLK, 256, REC_SMEM>>>(fW1 + (size_t)H * G4, bW1 + (size_t)H * G4,
                                          Xg0, Xg1, H1f, H1b, 1);
    assemble<<<B * T, 256>>>(H1f, H1b, out);
}